// round 2
// baseline (speedup 1.0000x reference)
#include <cuda_runtime.h>
#include <cstdint>
#include <cstdio>

#define T_STEPS 512
#define BATCH   128
#define DIM     512
#define M_ROWS  (T_STEPS * BATCH)   // 65536

// Scratch (static device allocations are the sanctioned scratch mechanism)
__device__ float g_xproj[(size_t)T_STEPS * BATCH * DIM];  // 134 MB
__device__ float g_h[2][BATCH * DIM];                     // double-buffered h

// ============================================================================
// Kernel 1: Xproj[m][n] = sum_k X[m][k] * W_in[n][k]
// fp32 double-buffered SMEM GEMM, 128x128 block, BK=16, 256 threads, 8x8 micro
// ============================================================================
__global__ void __launch_bounds__(256, 2)
xproj_gemm(const float* __restrict__ A, const float* __restrict__ W) {
    __shared__ float As[2][16][132];
    __shared__ float Bs[2][16][132];

    const int tid = threadIdx.x;
    const int tx = tid & 15;        // n direction (16)
    const int ty = tid >> 4;        // m direction (16)
    const int m0 = blockIdx.y * 128;
    const int n0 = blockIdx.x * 128;

    float acc[8][8];
#pragma unroll
    for (int i = 0; i < 8; i++)
#pragma unroll
        for (int j = 0; j < 8; j++) acc[i][j] = 0.0f;

    float4 ra[2], rb[2];

    // ---- prologue: load k-chunk 0 ----
#pragma unroll
    for (int j = 0; j < 2; j++) {
        int i  = tid + j * 256;          // float4 index within 512
        int rr = i >> 2;                 // row 0..127
        int kk = (i & 3) << 2;           // k offset 0,4,8,12
        ra[j] = *(const float4*)(A + (size_t)(m0 + rr) * 512 + kk);
        rb[j] = *(const float4*)(W + (size_t)(n0 + rr) * 512 + kk);
    }
#pragma unroll
    for (int j = 0; j < 2; j++) {
        int i  = tid + j * 256;
        int rr = i >> 2;
        int kk = (i & 3) << 2;
        As[0][kk + 0][rr] = ra[j].x; As[0][kk + 1][rr] = ra[j].y;
        As[0][kk + 2][rr] = ra[j].z; As[0][kk + 3][rr] = ra[j].w;
        Bs[0][kk + 0][rr] = rb[j].x; Bs[0][kk + 1][rr] = rb[j].y;
        Bs[0][kk + 2][rr] = rb[j].z; Bs[0][kk + 3][rr] = rb[j].w;
    }
    __syncthreads();

    for (int s = 0; s < 32; s++) {
        const int cb = s & 1;
        // prefetch next k-chunk into registers
        if (s < 31) {
            const int kc = (s + 1) * 16;
#pragma unroll
            for (int j = 0; j < 2; j++) {
                int i  = tid + j * 256;
                int rr = i >> 2;
                int kk = (i & 3) << 2;
                ra[j] = *(const float4*)(A + (size_t)(m0 + rr) * 512 + kc + kk);
                rb[j] = *(const float4*)(W + (size_t)(n0 + rr) * 512 + kc + kk);
            }
        }
        // compute current chunk
#pragma unroll
        for (int k = 0; k < 16; k++) {
            float4 a0 = *(const float4*)&As[cb][k][ty * 8];
            float4 a1 = *(const float4*)&As[cb][k][ty * 8 + 4];
            float4 b0 = *(const float4*)&Bs[cb][k][tx * 8];
            float4 b1 = *(const float4*)&Bs[cb][k][tx * 8 + 4];
            float av[8] = {a0.x, a0.y, a0.z, a0.w, a1.x, a1.y, a1.z, a1.w};
            float bv[8] = {b0.x, b0.y, b0.z, b0.w, b1.x, b1.y, b1.z, b1.w};
#pragma unroll
            for (int i = 0; i < 8; i++)
#pragma unroll
                for (int j = 0; j < 8; j++)
                    acc[i][j] = fmaf(av[i], bv[j], acc[i][j]);
        }
        // stage next chunk into the other buffer
        if (s < 31) {
            const int nb = (s + 1) & 1;
#pragma unroll
            for (int j = 0; j < 2; j++) {
                int i  = tid + j * 256;
                int rr = i >> 2;
                int kk = (i & 3) << 2;
                As[nb][kk + 0][rr] = ra[j].x; As[nb][kk + 1][rr] = ra[j].y;
                As[nb][kk + 2][rr] = ra[j].z; As[nb][kk + 3][rr] = ra[j].w;
                Bs[nb][kk + 0][rr] = rb[j].x; Bs[nb][kk + 1][rr] = rb[j].y;
                Bs[nb][kk + 2][rr] = rb[j].z; Bs[nb][kk + 3][rr] = rb[j].w;
            }
        }
        __syncthreads();
    }

    // epilogue
#pragma unroll
    for (int i = 0; i < 8; i++) {
        float4 o0 = make_float4(acc[i][0], acc[i][1], acc[i][2], acc[i][3]);
        float4 o1 = make_float4(acc[i][4], acc[i][5], acc[i][6], acc[i][7]);
        float* cp = g_xproj + (size_t)(m0 + ty * 8 + i) * 512 + n0 + tx * 8;
        *(float4*)cp       = o0;
        *(float4*)(cp + 4) = o1;
    }
}

// ============================================================================
// Kernel 2: sequential scan. 16 clusters of 8 CTAs (1 cluster = 1 batch-group
// of 8). CTA rank r owns output dims [r*64, r*64+64) with that W_h slice
// resident in SMEM. h exchanged via L2 (double-buffered g_h) + cluster barrier.
// ============================================================================
#define RED_ROUND(OFF, N)                                                     \
    {                                                                         \
        const bool hi_ = (lane & (OFF)) != 0;                                 \
        _Pragma("unroll")                                                     \
        for (int i_ = 0; i_ < (N); i_++) {                                    \
            float send_ = hi_ ? acc[i_] : acc[i_ + (N)];                      \
            float recv_ = __shfl_xor_sync(0xffffffffu, send_, (OFF));         \
            acc[i_] = (hi_ ? acc[i_ + (N)] : acc[i_]) + recv_;                \
        }                                                                     \
    }

__global__ void __cluster_dims__(8, 1, 1) __launch_bounds__(256, 1)
rnn_scan(const float* __restrict__ Wh, const float* __restrict__ bh,
         float* __restrict__ out) {
    extern __shared__ float smem[];
    float* Wt = smem;               // [64][512] W_h rows for this CTA
    float* hb = smem + 64 * 512;    // [8][512]  h(t) for this batch group

    const int tid  = threadIdx.x;
    const int lane = tid & 31;
    const int wid  = tid >> 5;      // warp 0..7 -> dims [wid*8, wid*8+8)
    const int r    = blockIdx.x & 7;    // cluster rank -> dim slice
    const int g    = blockIdx.x >> 3;   // batch group

    // load W_h slice (contiguous 128KB copy)
    {
        const float4* ws = (const float4*)(Wh + (size_t)(r * 64) * 512);
        float4* wd = (float4*)Wt;
        for (int i = tid; i < 64 * 512 / 4; i += 256) wd[i] = __ldg(ws + i);
    }
    // h(0) = 0
    {
        float4  z4  = make_float4(0.f, 0.f, 0.f, 0.f);
        float4* hd4 = (float4*)hb;
        for (int i = tid; i < 8 * 512 / 4; i += 256) hd4[i] = z4;
    }
    __syncthreads();

    // lane -> its two outputs j0 = 2*lane (= b*8 + d ordering)
    const int j0    = 2 * lane;
    const int bl    = j0 >> 3;            // local batch 0..7
    const int dl    = j0 & 7;             // local dim (even)
    const int dglob = r * 64 + wid * 8 + dl;
    const int bglob = g * 8 + bl;

    const float bias0 = bh[dglob];
    const float bias1 = bh[dglob + 1];
    const float* xp_ptr  = g_xproj + (size_t)bglob * DIM + dglob;
    float* hout0 = &g_h[0][bglob * DIM + dglob];
    float* hout1 = &g_h[1][bglob * DIM + dglob];
    const float* Wrow  = Wt + (wid * 8) * 512;
    const float* grp0  = g_h[0] + (size_t)g * 8 * DIM;
    const float* grp1  = g_h[1] + (size_t)g * 8 * DIM;
    float4* hd4 = (float4*)hb;

    for (int t = 0; t < T_STEPS; t++) {
        // prefetch xp(t) for this lane's two outputs (hidden behind compute)
        float2 xp = __ldg((const float2*)(xp_ptr + (size_t)t * BATCH * DIM));

        float acc[64];
#pragma unroll
        for (int i = 0; i < 64; i++) acc[i] = 0.0f;

        // K split across lanes: lane covers k = ki*32 + lane (conflict-free)
#pragma unroll 4
        for (int ki = 0; ki < 16; ki++) {
            const int k = ki * 32 + lane;
            float hv[8], wv[8];
#pragma unroll
            for (int b = 0; b < 8; b++) hv[b] = hb[b * 512 + k];
#pragma unroll
            for (int d = 0; d < 8; d++) wv[d] = Wrow[d * 512 + k];
#pragma unroll
            for (int b = 0; b < 8; b++)
#pragma unroll
                for (int d = 0; d < 8; d++)
                    acc[b * 8 + d] = fmaf(wv[d], hv[b], acc[b * 8 + d]);
        }

        // butterfly reduce: 64 partials over 32 lanes -> lane holds outputs
        // 2*lane and 2*lane+1 fully summed (62 SHFL total)
        RED_ROUND(16, 32)
        RED_ROUND(8, 16)
        RED_ROUND(4, 8)
        RED_ROUND(2, 4)
        RED_ROUND(1, 2)

        const float z0 = acc[0] + xp.x + bias0;
        const float z1 = acc[1] + xp.y + bias1;
        const float h0 = 1.0f / (1.0f + __expf(-z0));
        const float h1 = 1.0f / (1.0f + __expf(-z1));
        const float2 hh = make_float2(h0, h1);

        *(float2*)((t & 1) ? hout1 : hout0) = hh;
        if (t == T_STEPS - 1)
            *(float2*)(out + (size_t)bglob * DIM + dglob) = hh;

        __threadfence();
        asm volatile("barrier.cluster.arrive.aligned;\n" ::: "memory");
        asm volatile("barrier.cluster.wait.aligned;\n" ::: "memory");

        // refill full h(t+1) for the group from L2 (bypass L1)
        const float4* src = (const float4*)((t & 1) ? grp1 : grp0);
#pragma unroll
        for (int i = 0; i < 4; i++) {
            const int idx = tid + i * 256;
            hd4[idx] = __ldcg(src + idx);
        }
        __syncthreads();
    }
}

// ============================================================================
extern "C" void kernel_launch(void* const* d_in, const int* in_sizes, int n_in,
                              void* d_out, int out_size) {
    const float* X    = (const float*)d_in[0];  // [512,128,512]
    const float* W_in = (const float*)d_in[1];  // [512,512]
    const float* W_h  = (const float*)d_in[2];  // [512,512]
    const float* b_h  = (const float*)d_in[3];  // [512]
    float* out = (float*)d_out;                 // [128,512]

    (void)in_sizes; (void)n_in; (void)out_size;

    // Kernel 1: input projection GEMM
    dim3 g1(DIM / 128, M_ROWS / 128);   // (4, 512)
    xproj_gemm<<<g1, 256>>>(X, W_in);

    // Kernel 2: recurrent scan (128 CTAs = 16 clusters of 8)
    const int smem_bytes = (64 * 512 + 8 * 512) * (int)sizeof(float);  // 147456
    cudaFuncSetAttribute(rnn_scan,
                         cudaFuncAttributeMaxDynamicSharedMemorySize,
                         smem_bytes);
    rnn_scan<<<128, 256, smem_bytes>>>(W_h, b_h, out);
}

// round 3
// speedup vs baseline: 1.1371x; 1.1371x over previous
#include <cuda_runtime.h>
#include <cstdint>

#define T_STEPS 512
#define BATCH   128
#define DIM     512
#define M_ROWS  (T_STEPS * BATCH)   // 65536

typedef unsigned long long u64;

// Scratch
__device__ float g_xproj[(size_t)T_STEPS * BATCH * DIM];  // 134 MB

// ---------------------------------------------------------------------------
// packed f32x2 helpers (sm_103a; ptxas never emits FFMA2 from C++)
// ---------------------------------------------------------------------------
__device__ __forceinline__ u64 pack2(float lo, float hi) {
    u64 r;
    asm("mov.b64 %0, {%1, %2};" : "=l"(r) : "f"(lo), "f"(hi));
    return r;
}
__device__ __forceinline__ void unpack2(u64 v, float& lo, float& hi) {
    asm("mov.b64 {%0, %1}, %2;" : "=f"(lo), "=f"(hi) : "l"(v));
}
__device__ __forceinline__ u64 ffma2(u64 a, u64 b, u64 c) {
    u64 d;
    asm("fma.rn.f32x2 %0, %1, %2, %3;" : "=l"(d) : "l"(a), "l"(b), "l"(c));
    return d;
}
__device__ __forceinline__ u64 fadd2(u64 a, u64 b) {
    u64 d;
    asm("add.rn.f32x2 %0, %1, %2;" : "=l"(d) : "l"(a), "l"(b));
    return d;
}

// ============================================================================
// Kernel 1: Xproj[m][n] = sum_k X[m][k] * W_in[n][k]   (FFMA2 version)
// 128x128 block, BK=16, 256 threads, 8x8 micro (acc packed over n-pairs)
// ============================================================================
__global__ void __launch_bounds__(256, 2)
xproj_gemm(const float* __restrict__ A, const float* __restrict__ W) {
    __shared__ __align__(16) float As[2][16][132];
    __shared__ __align__(16) float Bs[2][16][132];

    const int tid = threadIdx.x;
    const int tx = tid & 15;
    const int ty = tid >> 4;
    const int m0 = blockIdx.y * 128;
    const int n0 = blockIdx.x * 128;

    u64 acc2[8][4];
#pragma unroll
    for (int i = 0; i < 8; i++)
#pragma unroll
        for (int j = 0; j < 4; j++) acc2[i][j] = 0ull;

    float4 ra[2], rb[2];

#pragma unroll
    for (int j = 0; j < 2; j++) {
        int i  = tid + j * 256;
        int rr = i >> 2;
        int kk = (i & 3) << 2;
        ra[j] = *(const float4*)(A + (size_t)(m0 + rr) * 512 + kk);
        rb[j] = *(const float4*)(W + (size_t)(n0 + rr) * 512 + kk);
    }
#pragma unroll
    for (int j = 0; j < 2; j++) {
        int i  = tid + j * 256;
        int rr = i >> 2;
        int kk = (i & 3) << 2;
        As[0][kk + 0][rr] = ra[j].x; As[0][kk + 1][rr] = ra[j].y;
        As[0][kk + 2][rr] = ra[j].z; As[0][kk + 3][rr] = ra[j].w;
        Bs[0][kk + 0][rr] = rb[j].x; Bs[0][kk + 1][rr] = rb[j].y;
        Bs[0][kk + 2][rr] = rb[j].z; Bs[0][kk + 3][rr] = rb[j].w;
    }
    __syncthreads();

    for (int s = 0; s < 32; s++) {
        const int cb = s & 1;
        if (s < 31) {
            const int kc = (s + 1) * 16;
#pragma unroll
            for (int j = 0; j < 2; j++) {
                int i  = tid + j * 256;
                int rr = i >> 2;
                int kk = (i & 3) << 2;
                ra[j] = *(const float4*)(A + (size_t)(m0 + rr) * 512 + kc + kk);
                rb[j] = *(const float4*)(W + (size_t)(n0 + rr) * 512 + kc + kk);
            }
        }
#pragma unroll
        for (int k = 0; k < 16; k++) {
            float4 a0 = *(const float4*)&As[cb][k][ty * 8];
            float4 a1 = *(const float4*)&As[cb][k][ty * 8 + 4];
            const ulonglong2* bp = (const ulonglong2*)&Bs[cb][k][tx * 8];
            ulonglong2 bq0 = bp[0];
            ulonglong2 bq1 = bp[1];
            u64 bb[4] = {bq0.x, bq0.y, bq1.x, bq1.y};
            float av[8] = {a0.x, a0.y, a0.z, a0.w, a1.x, a1.y, a1.z, a1.w};
#pragma unroll
            for (int i = 0; i < 8; i++) {
                u64 ad = pack2(av[i], av[i]);
                acc2[i][0] = ffma2(ad, bb[0], acc2[i][0]);
                acc2[i][1] = ffma2(ad, bb[1], acc2[i][1]);
                acc2[i][2] = ffma2(ad, bb[2], acc2[i][2]);
                acc2[i][3] = ffma2(ad, bb[3], acc2[i][3]);
            }
        }
        if (s < 31) {
            const int nb = (s + 1) & 1;
#pragma unroll
            for (int j = 0; j < 2; j++) {
                int i  = tid + j * 256;
                int rr = i >> 2;
                int kk = (i & 3) << 2;
                As[nb][kk + 0][rr] = ra[j].x; As[nb][kk + 1][rr] = ra[j].y;
                As[nb][kk + 2][rr] = ra[j].z; As[nb][kk + 3][rr] = ra[j].w;
                Bs[nb][kk + 0][rr] = rb[j].x; Bs[nb][kk + 1][rr] = rb[j].y;
                Bs[nb][kk + 2][rr] = rb[j].z; Bs[nb][kk + 3][rr] = rb[j].w;
            }
        }
        __syncthreads();
    }

#pragma unroll
    for (int i = 0; i < 8; i++) {
        float c0, c1, c2, c3, c4, c5, c6, c7;
        unpack2(acc2[i][0], c0, c1);
        unpack2(acc2[i][1], c2, c3);
        unpack2(acc2[i][2], c4, c5);
        unpack2(acc2[i][3], c6, c7);
        float* cp = g_xproj + (size_t)(m0 + ty * 8 + i) * 512 + n0 + tx * 8;
        *(float4*)cp       = make_float4(c0, c1, c2, c3);
        *(float4*)(cp + 4) = make_float4(c4, c5, c6, c7);
    }
}

// ============================================================================
// Kernel 2: recurrent scan. 16 clusters x 8 CTAs. CTA rank r owns dims
// [r*64, r*64+64), W_h slice d-pair-interleaved in SMEM. h exchanged via
// st.shared::cluster (DSMEM) ordered by barrier.cluster (release/acquire).
// ============================================================================
#define HB_BUF_BYTES 16384           // 8 batch x 512 dims x 4B
#define WT2_FLOATS   (64 * 512)      // 32768 floats = 128KB

// butterfly round on packed accumulators: OFF == count
#define RED2(OFF)                                                             \
    {                                                                         \
        const bool hi_ = (lane & (OFF)) != 0;                                 \
        _Pragma("unroll")                                                     \
        for (int i_ = 0; i_ < (OFF); i_++) {                                  \
            u64 send_ = hi_ ? acc2[i_] : acc2[i_ + (OFF)];                    \
            float sl_, sh_;                                                   \
            unpack2(send_, sl_, sh_);                                         \
            sl_ = __shfl_xor_sync(0xffffffffu, sl_, (OFF));                   \
            sh_ = __shfl_xor_sync(0xffffffffu, sh_, (OFF));                   \
            u64 keep_ = hi_ ? acc2[i_ + (OFF)] : acc2[i_];                    \
            acc2[i_] = fadd2(keep_, pack2(sl_, sh_));                         \
        }                                                                     \
    }

__global__ void __cluster_dims__(8, 1, 1) __launch_bounds__(256, 1)
rnn_scan(const float* __restrict__ Wh, const float* __restrict__ bh,
         float* __restrict__ out) {
    extern __shared__ __align__(16) float smem[];
    float* Wt = smem;                    // d-pair interleaved W_h slice
    float* hb = smem + WT2_FLOATS;       // [2][8][512] double-buffered h

    const int tid  = threadIdx.x;
    const int lane = tid & 31;
    const int wid  = tid >> 5;           // warp -> dims [wid*8, wid*8+8)
    const int r    = blockIdx.x & 7;     // cluster rank -> dim slice
    const int g    = blockIdx.x >> 3;    // batch group

    // ---- load W_h slice, interleaved by d-pairs:
    // Wt[p*1024 + 2k + parity] = W_h[r*64 + 2p + parity][k]
    for (int idx = tid; idx < 64 * 512 / 4; idx += 256) {
        int dl = idx >> 7;               // local dim 0..63
        int k4 = (idx & 127) << 2;       // k, step 4
        float4 v = __ldg((const float4*)(Wh + (size_t)(r * 64 + dl) * 512 + k4));
        float* wdst = Wt + (dl >> 1) * 1024 + (dl & 1);
        wdst[2 * (k4 + 0)] = v.x;
        wdst[2 * (k4 + 1)] = v.y;
        wdst[2 * (k4 + 2)] = v.z;
        wdst[2 * (k4 + 3)] = v.w;
    }
    // ---- zero ONLY buffer 0 (buffer 1 is written remotely at t=0)
    {
        float4  z4  = make_float4(0.f, 0.f, 0.f, 0.f);
        float4* hd4 = (float4*)hb;
        for (int i = tid; i < 8 * 512 / 4; i += 256) hd4[i] = z4;
    }
    __syncthreads();

    // lane j -> outputs (b = j>>2, d = wid*8 + (j&3)*2 .. +1)
    const int bl    = lane >> 2;
    const int dl2   = (lane & 3) * 2;
    const int dglob = r * 64 + wid * 8 + dl2;
    const int bglob = g * 8 + bl;

    const u64 bias2 = pack2(bh[dglob], bh[dglob + 1]);
    const float* xp_ptr = g_xproj + (size_t)bglob * DIM + dglob;

    // DSMEM destinations: this thread's float2 slot in every rank's hb
    uint32_t hb_u32;
    {
        size_t gp = __cvta_generic_to_shared(hb);
        hb_u32 = (uint32_t)gp;
    }
    const uint32_t slot_off = (uint32_t)(bl * 2048 + dglob * 4);
    uint32_t dst[8];
#pragma unroll
    for (int rr = 0; rr < 8; rr++) {
        asm("mapa.shared::cluster.u32 %0, %1, %2;"
            : "=r"(dst[rr]) : "r"(hb_u32 + slot_off), "r"(rr));
    }

    const float* WtW = Wt + (wid * 4) * 1024;   // this warp's 4 d-pair rows

    for (int t = 0; t < T_STEPS; t++) {
        const int p = t & 1;
        const float* hbp = hb + p * 4096;       // read buffer (floats)

        // prefetch xp(t) early (consumed ~2k cycles later)
        float2 xp = __ldg((const float2*)(xp_ptr + (size_t)t * BATCH * DIM));

        u64 acc2[32];
#pragma unroll
        for (int i = 0; i < 32; i++) acc2[i] = 0ull;

        // k split over lanes: lane covers k = ki*64 + lane*2 (+1)
#pragma unroll 2
        for (int ki = 0; ki < 8; ki++) {
            const int k = ki * 64 + lane * 2;
            // W d-pair vectors at k and k+1, for the warp's 4 d-pairs
            u64 w0[4], w1[4];
#pragma unroll
            for (int dd = 0; dd < 4; dd++) {
                ulonglong2 wq = *(const ulonglong2*)(WtW + dd * 1024 + 2 * k);
                w0[dd] = wq.x;   // (W[d][k],   W[d+1][k])
                w1[dd] = wq.y;   // (W[d][k+1], W[d+1][k+1])
            }
#pragma unroll
            for (int b = 0; b < 8; b++) {
                float2 hv = *(const float2*)(hbp + b * 512 + k);
                u64 hd0 = pack2(hv.x, hv.x);
                u64 hd1 = pack2(hv.y, hv.y);
#pragma unroll
                for (int dd = 0; dd < 4; dd++) {
                    acc2[b * 4 + dd] = ffma2(hd0, w0[dd], acc2[b * 4 + dd]);
                    acc2[b * 4 + dd] = ffma2(hd1, w1[dd], acc2[b * 4 + dd]);
                }
            }
        }

        // butterfly: 32 packed pairs over 32 lanes -> lane j holds pair j
        RED2(16) RED2(8) RED2(4) RED2(2) RED2(1)

        // z = acc + xp + bias; h = sigmoid(z)
        u64 z2 = fadd2(fadd2(acc2[0], pack2(xp.x, xp.y)), bias2);
        float z0, z1;
        unpack2(z2, z0, z1);
        const float h0 = 1.0f / (1.0f + __expf(-z0));
        const float h1 = 1.0f / (1.0f + __expf(-z1));
        const u64 hh = pack2(h0, h1);

        if (t < T_STEPS - 1) {
            // push this float2 into every rank's write buffer via DSMEM
            const uint32_t boff = (uint32_t)((p ^ 1) * HB_BUF_BYTES);
#pragma unroll
            for (int rr = 0; rr < 8; rr++) {
                asm volatile("st.shared::cluster.u64 [%0], %1;"
                             :: "r"(dst[rr] + boff), "l"(hh) : "memory");
            }
            // release own stores / acquire peers' stores
            asm volatile("barrier.cluster.arrive.aligned;" ::: "memory");
            asm volatile("barrier.cluster.wait.aligned;"   ::: "memory");
        } else {
            *(float2*)(out + (size_t)bglob * DIM + dglob) = make_float2(h0, h1);
        }
    }
}

// ============================================================================
extern "C" void kernel_launch(void* const* d_in, const int* in_sizes, int n_in,
                              void* d_out, int out_size) {
    const float* X    = (const float*)d_in[0];  // [512,128,512]
    const float* W_in = (const float*)d_in[1];  // [512,512]
    const float* W_h  = (const float*)d_in[2];  // [512,512]
    const float* b_h  = (const float*)d_in[3];  // [512]
    float* out = (float*)d_out;                 // [128,512]

    (void)in_sizes; (void)n_in; (void)out_size;

    dim3 g1(DIM / 128, M_ROWS / 128);   // (4, 512)
    xproj_gemm<<<g1, 256>>>(X, W_in);

    const int smem_bytes = (WT2_FLOATS + 2 * 8 * 512) * (int)sizeof(float); // 163840
    cudaFuncSetAttribute(rnn_scan,
                         cudaFuncAttributeMaxDynamicSharedMemorySize,
                         smem_bytes);
    rnn_scan<<<128, 256, smem_bytes>>>(W_h, b_h, out);
}

// round 4
// speedup vs baseline: 1.1415x; 1.0039x over previous
#include <cuda_runtime.h>
#include <cstdint>

#define T_STEPS 512
#define BATCH   128
#define DIM     512
#define M_ROWS  (T_STEPS * BATCH)   // 65536

typedef unsigned long long u64;

// Scratch
__device__ float g_xproj[(size_t)T_STEPS * BATCH * DIM];  // 134 MB

// ---------------------------------------------------------------------------
// packed f32x2 helpers (sm_103a; ptxas never emits FFMA2 from C++)
// ---------------------------------------------------------------------------
__device__ __forceinline__ u64 pack2(float lo, float hi) {
    u64 r;
    asm("mov.b64 %0, {%1, %2};" : "=l"(r) : "f"(lo), "f"(hi));
    return r;
}
__device__ __forceinline__ void unpack2(u64 v, float& lo, float& hi) {
    asm("mov.b64 {%0, %1}, %2;" : "=f"(lo), "=f"(hi) : "l"(v));
}
__device__ __forceinline__ u64 ffma2(u64 a, u64 b, u64 c) {
    u64 d;
    asm("fma.rn.f32x2 %0, %1, %2, %3;" : "=l"(d) : "l"(a), "l"(b), "l"(c));
    return d;
}
__device__ __forceinline__ u64 fadd2(u64 a, u64 b) {
    u64 d;
    asm("add.rn.f32x2 %0, %1, %2;" : "=l"(d) : "l"(a), "l"(b));
    return d;
}

// ============================================================================
// Kernel 1: Xproj[m][n] = sum_k X[m][k] * W_in[n][k]   (FFMA2 version)
// 128x128 block, BK=16, 256 threads, 8x8 micro (acc packed over n-pairs)
// ============================================================================
__global__ void __launch_bounds__(256, 2)
xproj_gemm(const float* __restrict__ A, const float* __restrict__ W) {
    __shared__ __align__(16) float As[2][16][132];
    __shared__ __align__(16) float Bs[2][16][132];

    const int tid = threadIdx.x;
    const int tx = tid & 15;
    const int ty = tid >> 4;
    const int m0 = blockIdx.y * 128;
    const int n0 = blockIdx.x * 128;

    u64 acc2[8][4];
#pragma unroll
    for (int i = 0; i < 8; i++)
#pragma unroll
        for (int j = 0; j < 4; j++) acc2[i][j] = 0ull;

    float4 ra[2], rb[2];

#pragma unroll
    for (int j = 0; j < 2; j++) {
        int i  = tid + j * 256;
        int rr = i >> 2;
        int kk = (i & 3) << 2;
        ra[j] = *(const float4*)(A + (size_t)(m0 + rr) * 512 + kk);
        rb[j] = *(const float4*)(W + (size_t)(n0 + rr) * 512 + kk);
    }
#pragma unroll
    for (int j = 0; j < 2; j++) {
        int i  = tid + j * 256;
        int rr = i >> 2;
        int kk = (i & 3) << 2;
        As[0][kk + 0][rr] = ra[j].x; As[0][kk + 1][rr] = ra[j].y;
        As[0][kk + 2][rr] = ra[j].z; As[0][kk + 3][rr] = ra[j].w;
        Bs[0][kk + 0][rr] = rb[j].x; Bs[0][kk + 1][rr] = rb[j].y;
        Bs[0][kk + 2][rr] = rb[j].z; Bs[0][kk + 3][rr] = rb[j].w;
    }
    __syncthreads();

    for (int s = 0; s < 32; s++) {
        const int cb = s & 1;
        if (s < 31) {
            const int kc = (s + 1) * 16;
#pragma unroll
            for (int j = 0; j < 2; j++) {
                int i  = tid + j * 256;
                int rr = i >> 2;
                int kk = (i & 3) << 2;
                ra[j] = *(const float4*)(A + (size_t)(m0 + rr) * 512 + kc + kk);
                rb[j] = *(const float4*)(W + (size_t)(n0 + rr) * 512 + kc + kk);
            }
        }
#pragma unroll
        for (int k = 0; k < 16; k++) {
            float4 a0 = *(const float4*)&As[cb][k][ty * 8];
            float4 a1 = *(const float4*)&As[cb][k][ty * 8 + 4];
            const ulonglong2* bp = (const ulonglong2*)&Bs[cb][k][tx * 8];
            ulonglong2 bq0 = bp[0];
            ulonglong2 bq1 = bp[1];
            u64 bb[4] = {bq0.x, bq0.y, bq1.x, bq1.y};
            float av[8] = {a0.x, a0.y, a0.z, a0.w, a1.x, a1.y, a1.z, a1.w};
#pragma unroll
            for (int i = 0; i < 8; i++) {
                u64 ad = pack2(av[i], av[i]);
                acc2[i][0] = ffma2(ad, bb[0], acc2[i][0]);
                acc2[i][1] = ffma2(ad, bb[1], acc2[i][1]);
                acc2[i][2] = ffma2(ad, bb[2], acc2[i][2]);
                acc2[i][3] = ffma2(ad, bb[3], acc2[i][3]);
            }
        }
        if (s < 31) {
            const int nb = (s + 1) & 1;
#pragma unroll
            for (int j = 0; j < 2; j++) {
                int i  = tid + j * 256;
                int rr = i >> 2;
                int kk = (i & 3) << 2;
                As[nb][kk + 0][rr] = ra[j].x; As[nb][kk + 1][rr] = ra[j].y;
                As[nb][kk + 2][rr] = ra[j].z; As[nb][kk + 3][rr] = ra[j].w;
                Bs[nb][kk + 0][rr] = rb[j].x; Bs[nb][kk + 1][rr] = rb[j].y;
                Bs[nb][kk + 2][rr] = rb[j].z; Bs[nb][kk + 3][rr] = rb[j].w;
            }
        }
        __syncthreads();
    }

#pragma unroll
    for (int i = 0; i < 8; i++) {
        float c0, c1, c2, c3, c4, c5, c6, c7;
        unpack2(acc2[i][0], c0, c1);
        unpack2(acc2[i][1], c2, c3);
        unpack2(acc2[i][2], c4, c5);
        unpack2(acc2[i][3], c6, c7);
        float* cp = g_xproj + (size_t)(m0 + ty * 8 + i) * 512 + n0 + tx * 8;
        *(float4*)cp       = make_float4(c0, c1, c2, c3);
        *(float4*)(cp + 4) = make_float4(c4, c5, c6, c7);
    }
}

// ============================================================================
// Kernel 2: recurrent scan. 16 clusters x 8 CTAs. CTA rank r owns dims
// [r*64, r*64+64), W_h slice d-pair-interleaved in SMEM. h exchanged via
// st.shared::cluster (DSMEM) ordered by barrier.cluster (release/acquire).
// ============================================================================
#define HB_BUF_BYTES 16384           // 8 batch x 512 dims x 4B
#define WT2_FLOATS   (64 * 512)      // 32768 floats = 128KB

// butterfly round on packed accumulators: OFF == count
#define RED2(OFF)                                                             \
    {                                                                         \
        const bool hi_ = (lane & (OFF)) != 0;                                 \
        _Pragma("unroll")                                                     \
        for (int i_ = 0; i_ < (OFF); i_++) {                                  \
            u64 send_ = hi_ ? acc2[i_] : acc2[i_ + (OFF)];                    \
            float sl_, sh_;                                                   \
            unpack2(send_, sl_, sh_);                                         \
            sl_ = __shfl_xor_sync(0xffffffffu, sl_, (OFF));                   \
            sh_ = __shfl_xor_sync(0xffffffffu, sh_, (OFF));                   \
            u64 keep_ = hi_ ? acc2[i_ + (OFF)] : acc2[i_];                    \
            acc2[i_] = fadd2(keep_, pack2(sl_, sh_));                         \
        }                                                                     \
    }

__global__ void __cluster_dims__(8, 1, 1) __launch_bounds__(256, 1)
rnn_scan(const float* __restrict__ Wh, const float* __restrict__ bh,
         float* __restrict__ out) {
    extern __shared__ __align__(16) float smem[];
    float* Wt = smem;                    // d-pair interleaved W_h slice
    float* hb = smem + WT2_FLOATS;       // [2][8][512] double-buffered h

    const int tid  = threadIdx.x;
    const int lane = tid & 31;
    const int wid  = tid >> 5;           // warp -> dims [wid*8, wid*8+8)
    const int r    = blockIdx.x & 7;     // cluster rank -> dim slice
    const int g    = blockIdx.x >> 3;    // batch group

    // ---- load W_h slice, interleaved by d-pairs:
    // Wt[p*1024 + 2k + parity] = W_h[r*64 + 2p + parity][k]
    for (int idx = tid; idx < 64 * 512 / 4; idx += 256) {
        int dl = idx >> 7;               // local dim 0..63
        int k4 = (idx & 127) << 2;       // k, step 4
        float4 v = __ldg((const float4*)(Wh + (size_t)(r * 64 + dl) * 512 + k4));
        float* wdst = Wt + (dl >> 1) * 1024 + (dl & 1);
        wdst[2 * (k4 + 0)] = v.x;
        wdst[2 * (k4 + 1)] = v.y;
        wdst[2 * (k4 + 2)] = v.z;
        wdst[2 * (k4 + 3)] = v.w;
    }
    // ---- zero ONLY buffer 0 (buffer 1 is written remotely at t=0)
    {
        float4  z4  = make_float4(0.f, 0.f, 0.f, 0.f);
        float4* hd4 = (float4*)hb;
        for (int i = tid; i < 8 * 512 / 4; i += 256) hd4[i] = z4;
    }
    __syncthreads();

    // lane j -> outputs (b = j>>2, d = wid*8 + (j&3)*2 .. +1)
    const int bl    = lane >> 2;
    const int dl2   = (lane & 3) * 2;
    const int dglob = r * 64 + wid * 8 + dl2;
    const int bglob = g * 8 + bl;

    const u64 bias2 = pack2(bh[dglob], bh[dglob + 1]);
    const float* xp_ptr = g_xproj + (size_t)bglob * DIM + dglob;

    // DSMEM destinations: this thread's float2 slot in every rank's hb
    uint32_t hb_u32;
    {
        size_t gp = __cvta_generic_to_shared(hb);
        hb_u32 = (uint32_t)gp;
    }
    const uint32_t slot_off = (uint32_t)(bl * 2048 + dglob * 4);
    uint32_t dst[8];
#pragma unroll
    for (int rr = 0; rr < 8; rr++) {
        asm("mapa.shared::cluster.u32 %0, %1, %2;"
            : "=r"(dst[rr]) : "r"(hb_u32 + slot_off), "r"(rr));
    }

    const float* WtW = Wt + (wid * 4) * 1024;   // this warp's 4 d-pair rows

    for (int t = 0; t < T_STEPS; t++) {
        const int p = t & 1;
        const float* hbp = hb + p * 4096;       // read buffer (floats)

        // prefetch xp(t) early (consumed ~2k cycles later)
        float2 xp = __ldg((const float2*)(xp_ptr + (size_t)t * BATCH * DIM));

        u64 acc2[32];
#pragma unroll
        for (int i = 0; i < 32; i++) acc2[i] = 0ull;

        // k split over lanes: lane covers k = ki*64 + lane*2 (+1)
#pragma unroll 2
        for (int ki = 0; ki < 8; ki++) {
            const int k = ki * 64 + lane * 2;
            // W d-pair vectors at k and k+1, for the warp's 4 d-pairs
            u64 w0[4], w1[4];
#pragma unroll
            for (int dd = 0; dd < 4; dd++) {
                ulonglong2 wq = *(const ulonglong2*)(WtW + dd * 1024 + 2 * k);
                w0[dd] = wq.x;   // (W[d][k],   W[d+1][k])
                w1[dd] = wq.y;   // (W[d][k+1], W[d+1][k+1])
            }
#pragma unroll
            for (int b = 0; b < 8; b++) {
                float2 hv = *(const float2*)(hbp + b * 512 + k);
                u64 hd0 = pack2(hv.x, hv.x);
                u64 hd1 = pack2(hv.y, hv.y);
#pragma unroll
                for (int dd = 0; dd < 4; dd++) {
                    acc2[b * 4 + dd] = ffma2(hd0, w0[dd], acc2[b * 4 + dd]);
                    acc2[b * 4 + dd] = ffma2(hd1, w1[dd], acc2[b * 4 + dd]);
                }
            }
        }

        // butterfly: 32 packed pairs over 32 lanes -> lane j holds pair j
        RED2(16) RED2(8) RED2(4) RED2(2) RED2(1)

        // z = acc + xp + bias; h = sigmoid(z)
        u64 z2 = fadd2(fadd2(acc2[0], pack2(xp.x, xp.y)), bias2);
        float z0, z1;
        unpack2(z2, z0, z1);
        const float h0 = 1.0f / (1.0f + __expf(-z0));
        const float h1 = 1.0f / (1.0f + __expf(-z1));
        const u64 hh = pack2(h0, h1);

        if (t < T_STEPS - 1) {
            // push this float2 into every rank's write buffer via DSMEM
            const uint32_t boff = (uint32_t)((p ^ 1) * HB_BUF_BYTES);
#pragma unroll
            for (int rr = 0; rr < 8; rr++) {
                asm volatile("st.shared::cluster.u64 [%0], %1;"
                             :: "r"(dst[rr] + boff), "l"(hh) : "memory");
            }
            // release own stores / acquire peers' stores
            asm volatile("barrier.cluster.arrive.aligned;" ::: "memory");
            asm volatile("barrier.cluster.wait.aligned;"   ::: "memory");
        } else {
            *(float2*)(out + (size_t)bglob * DIM + dglob) = make_float2(h0, h1);
        }
    }
}

// ============================================================================
extern "C" void kernel_launch(void* const* d_in, const int* in_sizes, int n_in,
                              void* d_out, int out_size) {
    const float* X    = (const float*)d_in[0];  // [512,128,512]
    const float* W_in = (const float*)d_in[1];  // [512,512]
    const float* W_h  = (const float*)d_in[2];  // [512,512]
    const float* b_h  = (const float*)d_in[3];  // [512]
    float* out = (float*)d_out;                 // [128,512]

    (void)in_sizes; (void)n_in; (void)out_size;

    dim3 g1(DIM / 128, M_ROWS / 128);   // (4, 512)
    xproj_gemm<<<g1, 256>>>(X, W_in);

    const int smem_bytes = (WT2_FLOATS + 2 * 8 * 512) * (int)sizeof(float); // 163840
    cudaFuncSetAttribute(rnn_scan,
                         cudaFuncAttributeMaxDynamicSharedMemorySize,
                         smem_bytes);
    rnn_scan<<<128, 256, smem_bytes>>>(W_h, b_h, out);
}